// round 1
// baseline (speedup 1.0000x reference)
#include <cuda_runtime.h>

// MultiPartLoss: YOLO-style loss over (N, 49, 30) preds/targets, fp32.
// Layout per cell (30 floats): [20 class probs][2 conf][2 boxes x (x,y,w,h)]
// Strategy: stream both tensors once, coalesced float4 -> smem tile,
// thread-per-cell compute, hierarchical reduction, scalar out = loss / N.

#define C_CLS 20
#define F 30            // floats per cell
#define TPB 192         // threads per block == cells per tile
#define TILE_FLOATS (TPB * F)   // 5760 floats = 23040 B per tensor
#define NBLK 592        // 148 SMs * 4 resident blocks (46KB smem/block)
#define NOOBJ 0.5f

__device__ float g_partials[NBLK];

__global__ __launch_bounds__(TPB) void mploss_main(
    const float* __restrict__ preds,
    const float* __restrict__ targets,
    int M)   // total cells
{
    __shared__ float sp[TILE_FLOATS];
    __shared__ float st[TILE_FLOATS];

    float acc = 0.0f;
    const int numTiles = (M + TPB - 1) / TPB;

    for (int tile = blockIdx.x; tile < numTiles; tile += gridDim.x) {
        const long long base = (long long)tile * TILE_FLOATS;
        const long long remaining = (long long)M * F - base;

        if (remaining >= TILE_FLOATS) {
            // Full tile: 23040-byte chunk, 16B-aligned (23040 % 16 == 0).
            const float4* p4 = (const float4*)(preds + base);
            const float4* t4 = (const float4*)(targets + base);
            float4* sp4 = (float4*)sp;
            float4* st4 = (float4*)st;
            #pragma unroll
            for (int i = threadIdx.x; i < TILE_FLOATS / 4; i += TPB) {
                sp4[i] = p4[i];
                st4[i] = t4[i];
            }
        } else {
            for (int i = threadIdx.x; i < (int)remaining; i += TPB) {
                sp[i] = preds[base + i];
                st[i] = targets[base + i];
            }
        }
        __syncthreads();

        const int cell = tile * TPB + threadIdx.x;
        if (cell < M) {
            const float* p = sp + threadIdx.x * F;
            const float* t = st + threadIdx.x * F;

            // no-object confidence term (both boxes, always)
            float dc0 = p[20] - t[20];
            float dc1 = p[21] - t[21];
            float l = NOOBJ * (dc0 * dc0 + dc1 * dc1);

            // obj flag: class targets are one-hot * obj -> sum is exactly 0 or 1
            float s = 0.0f;
            #pragma unroll
            for (int c = 0; c < C_CLS; c++) s += t[c];
            const bool obj = (s == 1.0f);

            if (obj) {
                // IoU for both boxes (stop_gradient -> plain value here)
                float iou[2];
                #pragma unroll
                for (int b = 0; b < 2; b++) {
                    const int o = 22 + 4 * b;
                    float px = p[o], py = p[o + 1], pw = p[o + 2], ph = p[o + 3];
                    float tx = t[o], ty = t[o + 1], tw = t[o + 2], th = t[o + 3];
                    float xA = fmaxf(px - pw * 0.5f, tx - tw * 0.5f);
                    float xB = fminf(px + pw * 0.5f, tx + tw * 0.5f);
                    float yA = fmaxf(py - ph * 0.5f, ty - th * 0.5f);
                    float yB = fminf(py + ph * 0.5f, ty + th * 0.5f);
                    float inter = fmaxf(0.0f, xB - xA + 1.0f) *
                                  fmaxf(0.0f, yB - yA + 1.0f);
                    float uni = pw * ph + tw * th - inter;
                    iou[b] = inter / uni;
                }
                // jnp.argmax: first max wins -> top = 1 only if strictly greater
                const int top = (iou[1] > iou[0]) ? 1 : 0;
                const int o = 22 + 4 * top;

                // responsible-box confidence
                float dct = p[20 + top] - t[20 + top];
                l += (1.0f - NOOBJ) * dct * dct;

                // class probabilities
                float cls = 0.0f;
                #pragma unroll
                for (int c = 0; c < C_CLS; c++) {
                    float d = p[c] - t[c];
                    cls += d * d;
                }
                l += cls;

                // xy
                float dx = p[o] - t[o];
                float dy = p[o + 1] - t[o + 1];
                l += dx * dx + dy * dy;

                // sqrt(wh)
                float dw = sqrtf(p[o + 2]) - sqrtf(t[o + 2]);
                float dh = sqrtf(p[o + 3]) - sqrtf(t[o + 3]);
                l += dw * dw + dh * dh;
            }
            acc += l;
        }
        __syncthreads();
    }

    // intra-warp reduce
    #pragma unroll
    for (int off = 16; off > 0; off >>= 1)
        acc += __shfl_down_sync(0xFFFFFFFFu, acc, off);

    __shared__ float warp_sums[TPB / 32];
    const int lane = threadIdx.x & 31;
    const int wid  = threadIdx.x >> 5;
    if (lane == 0) warp_sums[wid] = acc;
    __syncthreads();

    if (threadIdx.x == 0) {
        float bsum = 0.0f;
        #pragma unroll
        for (int w = 0; w < TPB / 32; w++) bsum += warp_sums[w];
        g_partials[blockIdx.x] = bsum;
    }
}

__global__ void mploss_finalize(float* __restrict__ out, float invN)
{
    __shared__ double ssum[256];
    double s = 0.0;
    for (int i = threadIdx.x; i < NBLK; i += 256)
        s += (double)g_partials[i];
    ssum[threadIdx.x] = s;
    __syncthreads();
    for (int stride = 128; stride > 0; stride >>= 1) {
        if (threadIdx.x < stride) ssum[threadIdx.x] += ssum[threadIdx.x + stride];
        __syncthreads();
    }
    if (threadIdx.x == 0) out[0] = (float)(ssum[0] * (double)invN);
}

extern "C" void kernel_launch(void* const* d_in, const int* in_sizes, int n_in,
                              void* d_out, int out_size)
{
    const float* preds   = (const float*)d_in[0];
    const float* targets = (const float*)d_in[1];
    float* out = (float*)d_out;

    const int M = in_sizes[0] / F;        // total grid cells
    const int N = M / 49;                 // batch size (S*S = 49)
    const float invN = 1.0f / (float)N;

    mploss_main<<<NBLK, TPB>>>(preds, targets, M);
    mploss_finalize<<<1, 256>>>(out, invN);
}